// round 15
// baseline (speedup 1.0000x reference)
#include <cuda_runtime.h>
#include <cuda_fp16.h>
#include <math.h>
#include <stdint.h>

#define BL     8192
#define DMODEL 1024
#define DLLM   4096
#define DINNER 1024
#define SEQ_S  1000
#define NHEAD  16
#define EDIM   64

// ---------------------------------------------------------------------------
// Portable PTX helpers (base compute_103 target — NO tcgen05)
// ---------------------------------------------------------------------------
__device__ __forceinline__ uint32_t smem_u32(const void* p) {
    uint32_t a;
    asm("{ .reg .u64 t; cvta.to.shared.u64 t, %1; cvt.u32.u64 %0, t; }"
        : "=r"(a) : "l"(p));
    return a;
}

#define SWZ(o) ((o) ^ (((o) >> 3) & 0x70))

#define CP_ASYNC16(dst, src) \
    asm volatile("cp.async.cg.shared.global [%0], [%1], 16;\n" :: "r"(dst), "l"(src))
#define CP_COMMIT() asm volatile("cp.async.commit_group;\n" ::: "memory")
#define CP_WAIT1()  asm volatile("cp.async.wait_group 1;\n" ::: "memory")
#define CP_WAIT2()  asm volatile("cp.async.wait_group 2;\n" ::: "memory")
#define CP_WAIT0()  asm volatile("cp.async.wait_group 0;\n" ::: "memory")
#define STS_ZERO16(addr) \
    asm volatile("st.shared.v4.b32 [%0], {%1,%1,%1,%1};\n" :: "r"(addr), "r"(0u) : "memory")

__device__ __forceinline__ void ldsm4(uint32_t* r, uint32_t a) {
    asm volatile("ldmatrix.sync.aligned.m8n8.x4.shared.b16 {%0,%1,%2,%3}, [%4];\n"
        : "=r"(r[0]), "=r"(r[1]), "=r"(r[2]), "=r"(r[3]) : "r"(a));
}
__device__ __forceinline__ void ldsm4t(uint32_t* r, uint32_t a) {
    asm volatile("ldmatrix.sync.aligned.m8n8.x4.trans.shared.b16 {%0,%1,%2,%3}, [%4];\n"
        : "=r"(r[0]), "=r"(r[1]), "=r"(r[2]), "=r"(r[3]) : "r"(a));
}
__device__ __forceinline__ void mma16816h(float* c, const uint32_t* a,
                                          uint32_t b0, uint32_t b1) {
    asm volatile(
        "mma.sync.aligned.m16n8k16.row.col.f32.f16.f16.f32 "
        "{%0,%1,%2,%3}, {%4,%5,%6,%7}, {%8,%9}, {%0,%1,%2,%3};\n"
        : "+f"(c[0]), "+f"(c[1]), "+f"(c[2]), "+f"(c[3])
        : "r"(a[0]), "r"(a[1]), "r"(a[2]), "r"(a[3]), "r"(b0), "r"(b1));
}

// ---------------------------------------------------------------------------
// Scratch (device globals — no allocation allowed) — ALL fp16 single
// ---------------------------------------------------------------------------
__device__ __half g_tf[BL * DMODEL];
__device__ __half g_sf[SEQ_S * DLLM];
__device__ __half g_vf[SEQ_S * DLLM];
__device__ __half g_qs[BL * DINNER], g_ql[BL * DINNER];
__device__ __half g_ks[SEQ_S * DINNER], g_vs[SEQ_S * DINNER];
__device__ __half g_kl[SEQ_S * DINNER], g_vl[SEQ_S * DINNER];
__device__ __half g_af0[BL * DINNER], g_af1[BL * DINNER], g_af16[BL * DINNER];
__device__ __half g_wqs[DINNER * DMODEL], g_wql[DINNER * DMODEL];
__device__ __half g_wks[DINNER * DLLM],   g_wvs[DINNER * DLLM];
__device__ __half g_wkl[DINNER * DLLM],   g_wvl[DINNER * DLLM];
__device__ __half g_wo[DLLM * DINNER];

// ---------------------------------------------------------------------------
// Merged prepass: 7 fp32->fp16 transposes + 3 fp32->fp16 flat converts.
// ---------------------------------------------------------------------------
struct PrepassParams {
    const float* W[7];
    __half* T[7];
    int K[7], N[7];
    int t_ofs[8];
    const float* X[3];
    __half* H[3];
    int s_ofs[4];
    int total_trans;
};

__global__ __launch_bounds__(256)
void prepass(PrepassParams p)
{
    __shared__ float tsm[32][33];
    const int bid = blockIdx.x;
    if (bid < p.total_trans) {
        int w = 0;
        while (bid >= p.t_ofs[w + 1]) w++;
        const int t = bid - p.t_ofs[w];
        const int K = p.K[w], N = p.N[w];
        const int tiles_x = N >> 5;
        const int n0 = (t % tiles_x) << 5, k0 = (t / tiles_x) << 5;
        const float* __restrict__ W = p.W[w];
        __half* __restrict__ T = p.T[w];
        const int tx = threadIdx.x & 31, ty = threadIdx.x >> 5;
#pragma unroll
        for (int i = 0; i < 32; i += 8)
            tsm[ty + i][tx] = W[(size_t)(k0 + ty + i) * N + n0 + tx];
        __syncthreads();
#pragma unroll
        for (int i = 0; i < 32; i += 8) {
            int n = n0 + ty + i;
            T[(size_t)n * K + k0 + tx] = __float2half(tsm[tx][ty + i]);
        }
    } else {
        const int sb = bid - p.total_trans;
        int a = 0;
        while (sb >= p.s_ofs[a + 1]) a++;
        const int rel = sb - p.s_ofs[a];
        const float* __restrict__ X = p.X[a];
        __half* __restrict__ H = p.H[a];
#pragma unroll
        for (int i = 0; i < 16; i++) {
            int idx = rel * 16384 + (i * 256 + threadIdx.x) * 4;
            float4 v = *(const float4*)(X + idx);
            __half2 h01 = __floats2half2_rn(v.x, v.y);
            __half2 h23 = __floats2half2_rn(v.z, v.w);
            uint2 o;
            o.x = *reinterpret_cast<uint32_t*>(&h01);
            o.y = *reinterpret_cast<uint32_t*>(&h23);
            *(uint2*)(H + idx) = o;
        }
    }
}

// combine: c = a + b (fp16x2, vectorized)
__global__ __launch_bounds__(256)
void add_f16(const __half2* __restrict__ a, const __half2* __restrict__ b,
             __half2* __restrict__ c, int n2)
{
    int i = blockIdx.x * blockDim.x + threadIdx.x;
    int stride = gridDim.x * blockDim.x;
    for (; i < n2; i += stride)
        c[i] = __hadd2(a[i], b[i]);
}

// ---------------------------------------------------------------------------
// fp16 single-term GEMM, 128x128 tile, BK=64, 3-stage (96KB) -> 2 CTAs/SM.
// ---------------------------------------------------------------------------
#define F_A 0
#define F_B 16384
#define FSTG 32768
#define GEMM_SMEM (3 * FSTG)   // 96 KB

struct ProjJobs {
    const __half *A[6], *B[6];
    const float* bias[6];
    __half* C[6];
    int M[6], K[6];
    int ofs[7];
};

__global__ __launch_bounds__(256, 2)
void gemm_proj_f16(ProjJobs p)
{
    extern __shared__ __align__(1024) char smem[];
    const int bid = blockIdx.x;
    int z = 0;
    while (bid >= p.ofs[z + 1]) z++;
    const int rel = bid - p.ofs[z];
    const int bx = rel & 7, by = rel >> 3;
    const int M = p.M[z], K = p.K[z];
    const int N = DINNER;

    const __half* __restrict__ A = p.A[z];
    const __half* __restrict__ B = p.B[z];

    const int tid = threadIdx.x;
    const int wid = tid >> 5, lid = tid & 31;
    const int wm = wid & 3, wn = wid >> 2;
    const int m0 = by * 128, n0 = bx * 128;
    const uint32_t sb = smem_u32(smem);
    const int NC = K >> 6;

    float c[2][8][4];
#pragma unroll
    for (int i = 0; i < 2; i++)
#pragma unroll
        for (int j = 0; j < 8; j++)
#pragma unroll
            for (int q = 0; q < 4; q++) c[i][j][q] = 0.f;

    auto load_stage = [&](int cchunk) {
        const uint32_t st_ = sb + (cchunk % 3) * FSTG;
        const int k0_ = cchunk << 6;
#pragma unroll
        for (int i_ = 0; i_ < 4; i_++) {
            int idx_ = i_ * 256 + tid;
            int r_ = idx_ >> 3, u_ = idx_ & 7;
            uint32_t sw_ = SWZ((uint32_t)(r_ * 128 + u_ * 16));
            int gm_ = m0 + r_;
            if (gm_ < M)
                CP_ASYNC16(st_ + F_A + sw_, (const char*)(A + (size_t)gm_ * K + k0_) + u_ * 16);
            else
                STS_ZERO16(st_ + F_A + sw_);
            CP_ASYNC16(st_ + F_B + sw_, (const char*)(B + (size_t)(n0 + r_) * K + k0_) + u_ * 16);
        }
        CP_COMMIT();
    };

    load_stage(0);
    load_stage(1);

    const int q8 = lid >> 3, lr = lid & 7;

    for (int cc = 0; cc < NC; cc++) {
        CP_WAIT1();
        __syncthreads();
        if (cc + 2 < NC) { load_stage(cc + 2); } else { CP_COMMIT(); }

        const uint32_t st = sb + (cc % 3) * FSTG;
#pragma unroll
        for (int ks = 0; ks < 4; ks++) {
            const int kb = ks * 32;
            uint32_t ah[2][4], bh[8][2];
#pragma unroll
            for (int mi = 0; mi < 2; mi++) {
                uint32_t off = SWZ((uint32_t)(
                    (wm * 32 + mi * 16 + lr + (q8 & 1) * 8) * 128 + kb + (q8 >> 1) * 16));
                ldsm4(ah[mi], st + F_A + off);
            }
#pragma unroll
            for (int njp = 0; njp < 4; njp++) {
                uint32_t off = SWZ((uint32_t)(
                    (wn * 64 + njp * 16 + lr + (q8 >> 1) * 8) * 128 + kb + (q8 & 1) * 16));
                uint32_t t0[4];
                ldsm4(t0, st + F_B + off);
                bh[2 * njp][0] = t0[0]; bh[2 * njp][1] = t0[1];
                bh[2 * njp + 1][0] = t0[2]; bh[2 * njp + 1][1] = t0[3];
            }
#pragma unroll
            for (int mi = 0; mi < 2; mi++)
#pragma unroll
                for (int nj = 0; nj < 8; nj++)
                    mma16816h(c[mi][nj], ah[mi], bh[nj][0], bh[nj][1]);
        }
    }

    const int lr4 = lid >> 2, lc = (lid & 3) * 2;
    const float* __restrict__ bias = p.bias[z];
    __half* __restrict__ C = p.C[z];
#pragma unroll
    for (int mi = 0; mi < 2; mi++) {
        int row = m0 + wm * 32 + mi * 16 + lr4;
#pragma unroll
        for (int nj = 0; nj < 8; nj++) {
            int col = n0 + wn * 64 + nj * 8 + lc;
            float2 b2 = *(const float2*)(bias + col);
            __half2 h0 = __floats2half2_rn(c[mi][nj][0] + b2.x, c[mi][nj][1] + b2.y);
            __half2 h1 = __floats2half2_rn(c[mi][nj][2] + b2.x, c[mi][nj][3] + b2.y);
            if (row < M)
                *(uint32_t*)(C + (size_t)row * N + col) = *reinterpret_cast<uint32_t*>(&h0);
            if (row + 8 < M)
                *(uint32_t*)(C + (size_t)(row + 8) * N + col) = *reinterpret_cast<uint32_t*>(&h1);
        }
    }
}

__global__ __launch_bounds__(256, 2)
void gemm_out_f16(const __half* __restrict__ A, const __half* __restrict__ B,
                  const float* __restrict__ bias, float* __restrict__ C)
{
    extern __shared__ __align__(1024) char smem[];
    const int tid = threadIdx.x;
    const int wid = tid >> 5, lid = tid & 31;
    const int wm = wid & 3, wn = wid >> 2;
    const int m0 = blockIdx.y * 128, n0 = blockIdx.x * 128;
    const uint32_t sb = smem_u32(smem);
    const int K = DINNER, N = DLLM;
    const int NC = K >> 6;

    float c[2][8][4];
#pragma unroll
    for (int i = 0; i < 2; i++)
#pragma unroll
        for (int j = 0; j < 8; j++)
#pragma unroll
            for (int q = 0; q < 4; q++) c[i][j][q] = 0.f;

    auto load_stage = [&](int cchunk) {
        const uint32_t st_ = sb + (cchunk % 3) * FSTG;
        const int k0_ = cchunk << 6;
#pragma unroll
        for (int i_ = 0; i_ < 4; i_++) {
            int idx_ = i_ * 256 + tid;
            int r_ = idx_ >> 3, u_ = idx_ & 7;
            uint32_t sw_ = SWZ((uint32_t)(r_ * 128 + u_ * 16));
            CP_ASYNC16(st_ + F_A + sw_, (const char*)(A + (size_t)(m0 + r_) * K + k0_) + u_ * 16);
            CP_ASYNC16(st_ + F_B + sw_, (const char*)(B + (size_t)(n0 + r_) * K + k0_) + u_ * 16);
        }
        CP_COMMIT();
    };

    load_stage(0);
    load_stage(1);

    const int q8 = lid >> 3, lr = lid & 7;

    for (int cc = 0; cc < NC; cc++) {
        CP_WAIT1();
        __syncthreads();
        if (cc + 2 < NC) { load_stage(cc + 2); } else { CP_COMMIT(); }

        const uint32_t st = sb + (cc % 3) * FSTG;
#pragma unroll
        for (int ks = 0; ks < 4; ks++) {
            const int kb = ks * 32;
            uint32_t ah[2][4], bh[8][2];
#pragma unroll
            for (int mi = 0; mi < 2; mi++) {
                uint32_t off = SWZ((uint32_t)(
                    (wm * 32 + mi * 16 + lr + (q8 & 1) * 8) * 128 + kb + (q8 >> 1) * 16));
                ldsm4(ah[mi], st + F_A + off);
            }
#pragma unroll
            for (int njp = 0; njp < 4; njp++) {
                uint32_t off = SWZ((uint32_t)(
                    (wn * 64 + njp * 16 + lr + (q8 >> 1) * 8) * 128 + kb + (q8 & 1) * 16));
                uint32_t t0[4];
                ldsm4(t0, st + F_B + off);
                bh[2 * njp][0] = t0[0]; bh[2 * njp][1] = t0[1];
                bh[2 * njp + 1][0] = t0[2]; bh[2 * njp + 1][1] = t0[3];
            }
#pragma unroll
            for (int mi = 0; mi < 2; mi++)
#pragma unroll
                for (int nj = 0; nj < 8; nj++)
                    mma16816h(c[mi][nj], ah[mi], bh[nj][0], bh[nj][1]);
        }
    }

    const int lr4 = lid >> 2, lc = (lid & 3) * 2;
#pragma unroll
    for (int mi = 0; mi < 2; mi++) {
        int row = m0 + wm * 32 + mi * 16 + lr4;
#pragma unroll
        for (int nj = 0; nj < 8; nj++) {
            int col = n0 + wn * 64 + nj * 8 + lc;
            float2 b2 = *(const float2*)(bias + col);
            *(float2*)(C + (size_t)row * N + col) =
                make_float2(c[mi][nj][0] + b2.x, c[mi][nj][1] + b2.y);
            *(float2*)(C + (size_t)(row + 8) * N + col) =
                make_float2(c[mi][nj][2] + b2.x, c[mi][nj][3] + b2.y);
        }
    }
}

// ---------------------------------------------------------------------------
// HMMA flash attention: ONE stream per CTA (blockIdx.z), q-tile 128, 8 warps,
// 3-stage KV, 2 CTAs/SM. Max-free softmax + MUFU exp (R14 verified).
// Writes pre-scaled (alpha/l or beta/l) fp16 into its own buffer.
// ---------------------------------------------------------------------------
struct AttnParams {
    const __half *q[2], *k[2], *v[2];
    const float *alpha, *beta;
    __half *of[2];
};

#define ATT_STAGE 16384
#define A_K 0
#define A_V 8192
#define ATT_SMEM (3 * ATT_STAGE)   // 48 KB -> 2 CTAs/SM
#define NCH 16
#define SOFTMAX_SCALE 0.125f

__global__ __launch_bounds__(256, 2)
void attn_mma(AttnParams p)
{
    extern __shared__ __align__(1024) char smem[];
    const uint32_t sb = smem_u32(smem);
    const int tid = threadIdx.x;
    const int w = tid >> 5, lid = tid & 31;
    const int q8 = lid >> 3, lr = lid & 7;
    const int h = blockIdx.y;
    const int st = blockIdx.z;
    const int qbase = blockIdx.x * 128;
    const int colbase = h * EDIM;

    const __half* __restrict__ qp = p.q[st];
    const __half* __restrict__ kp = p.k[st];
    const __half* __restrict__ vp = p.v[st];
    const float wgt = (st == 0) ? *p.alpha : *p.beta;

    // ---- stage Q (128x64 = 16KB) into stage-2 region ----
    const uint32_t qst = sb + 2 * ATT_STAGE;
#pragma unroll
    for (int i = 0; i < 4; i++) {
        int idx = i * 256 + tid;
        int r = idx >> 3, u = idx & 7;
        uint32_t sw = SWZ((uint32_t)(r * 128 + u * 16));
        CP_ASYNC16(qst + sw,
                   (const char*)(qp + (size_t)(qbase + r) * DINNER + colbase) + u * 16);
    }
    CP_COMMIT();

#define LOAD_KV(cchunk) do { \
        const uint32_t stg_ = sb + ((cchunk) % 3) * ATT_STAGE; \
        const int s0_ = (cchunk) * 64; \
        _Pragma("unroll") \
        for (int i_ = 0; i_ < 2; i_++) { \
            int idx_ = i_ * 256 + tid; \
            int r_ = idx_ >> 3, u_ = idx_ & 7; \
            uint32_t sw_ = SWZ((uint32_t)(r_ * 128 + u_ * 16)); \
            if (s0_ + r_ < SEQ_S) { \
                const size_t go_ = (size_t)(s0_ + r_) * DINNER + colbase; \
                CP_ASYNC16(stg_ + A_K + sw_, (const char*)(kp + go_) + u_ * 16); \
                CP_ASYNC16(stg_ + A_V + sw_, (const char*)(vp + go_) + u_ * 16); \
            } else { \
                STS_ZERO16(stg_ + A_K + sw_); \
                STS_ZERO16(stg_ + A_V + sw_); \
            } \
        } \
        CP_COMMIT(); \
    } while (0)

    LOAD_KV(0);
    LOAD_KV(1);

    CP_WAIT2();            // Q complete
    __syncthreads();

    uint32_t qf[4][4];
#pragma unroll
    for (int ks = 0; ks < 4; ks++) {
        uint32_t off = SWZ((uint32_t)(
            (w * 16 + lr + (q8 & 1) * 8) * 128 + ks * 32 + (q8 >> 1) * 16));
        ldsm4(qf[ks], qst + off);
    }

    float o[8][4];
#pragma unroll
    for (int t = 0; t < 8; t++)
#pragma unroll
        for (int i = 0; i < 4; i++) o[t][i] = 0.f;
    float l0 = 0.f, l1 = 0.f;

    for (int cc = 0; cc < NCH; cc++) {
        CP_WAIT1();
        __syncthreads();
        if (cc + 2 < NCH) { LOAD_KV(cc + 2); } else { CP_COMMIT(); }
        const uint32_t stg = sb + (cc % 3) * ATT_STAGE;

        float s[8][4];
#pragma unroll
        for (int t = 0; t < 8; t++)
#pragma unroll
            for (int i = 0; i < 4; i++) s[t][i] = 0.f;

#pragma unroll
        for (int ks = 0; ks < 4; ks++) {
            uint32_t bh[8][2];
#pragma unroll
            for (int njp = 0; njp < 4; njp++) {
                uint32_t off = SWZ((uint32_t)(
                    (njp * 16 + lr + (q8 >> 1) * 8) * 128 + ks * 32 + (q8 & 1) * 16));
                uint32_t t0[4];
                ldsm4(t0, stg + A_K + off);
                bh[2 * njp][0] = t0[0]; bh[2 * njp][1] = t0[1];
                bh[2 * njp + 1][0] = t0[2]; bh[2 * njp + 1][1] = t0[3];
            }
#pragma unroll
            for (int t = 0; t < 8; t++)
                mma16816h(s[t], qf[ks], bh[t][0], bh[t][1]);
        }

        if (cc == NCH - 1) {
#pragma unroll
            for (int t = 5; t < 8; t++)
#pragma unroll
                for (int i = 0; i < 4; i++) s[t][i] = -1e30f;
        }

        // ---- softmax numerator: max-free, MUFU exp ----
#pragma unroll
        for (int t = 0; t < 8; t++) {
            float p0 = __expf(s[t][0] * SOFTMAX_SCALE);
            float p1 = __expf(s[t][1] * SOFTMAX_SCALE);
            float p2 = __expf(s[t][2] * SOFTMAX_SCALE);
            float p3 = __expf(s[t][3] * SOFTMAX_SCALE);
            l0 += p0 + p1; l1 += p2 + p3;
            s[t][0] = p0; s[t][1] = p1; s[t][2] = p2; s[t][3] = p3;
        }

#pragma unroll
        for (int ks = 0; ks < 4; ks++) {
            uint32_t pa[4];
            __half2 pp0 = __floats2half2_rn(s[2 * ks][0],     s[2 * ks][1]);
            __half2 pp1 = __floats2half2_rn(s[2 * ks][2],     s[2 * ks][3]);
            __half2 pp2 = __floats2half2_rn(s[2 * ks + 1][0], s[2 * ks + 1][1]);
            __half2 pp3 = __floats2half2_rn(s[2 * ks + 1][2], s[2 * ks + 1][3]);
            pa[0] = *reinterpret_cast<uint32_t*>(&pp0);
            pa[1] = *reinterpret_cast<uint32_t*>(&pp1);
            pa[2] = *reinterpret_cast<uint32_t*>(&pp2);
            pa[3] = *reinterpret_cast<uint32_t*>(&pp3);
#pragma unroll
            for (int ep = 0; ep < 4; ep++) {
                uint32_t off = SWZ((uint32_t)(
                    (ks * 16 + lr + (q8 & 1) * 8) * 128 + ep * 32 + (q8 >> 1) * 16));
                uint32_t tv0[4];
                ldsm4t(tv0, stg + A_V + off);
                mma16816h(o[2 * ep],     pa, tv0[0], tv0[1]);
                mma16816h(o[2 * ep + 1], pa, tv0[2], tv0[3]);
            }
        }
    }

    l0 += __shfl_xor_sync(0xffffffffu, l0, 1);
    l0 += __shfl_xor_sync(0xffffffffu, l0, 2);
    l1 += __shfl_xor_sync(0xffffffffu, l1, 1);
    l1 += __shfl_xor_sync(0xffffffffu, l1, 2);
    const float f0 = wgt / l0, f1 = wgt / l1;

    __half* __restrict__ of = p.of[st];
    const int r0 = qbase + w * 16 + (lid >> 2);
#pragma unroll
    for (int t = 0; t < 8; t++) {
        int col = colbase + t * 8 + (lid & 3) * 2;
        __half2 h0 = __floats2half2_rn(o[t][0] * f0, o[t][1] * f0);
        __half2 h1 = __floats2half2_rn(o[t][2] * f1, o[t][3] * f1);
        *(uint32_t*)(of + (size_t)r0 * DINNER + col) = *reinterpret_cast<uint32_t*>(&h0);
        *(uint32_t*)(of + (size_t)(r0 + 8) * DINNER + col) = *reinterpret_cast<uint32_t*>(&h1);
    }
}

// ---------------------------------------------------------------------------
// Launch
// ---------------------------------------------------------------------------
extern "C" void kernel_launch(void* const* d_in, const int* in_sizes, int n_in,
                              void* d_out, int out_size)
{
    const float* target = (const float*)d_in[0];
    const float* source = (const float*)d_in[1];
    const float* value  = (const float*)d_in[2];
    const float* Wq_s = (const float*)d_in[3];  const float* bq_s = (const float*)d_in[4];
    const float* Wk_s = (const float*)d_in[5];  const float* bk_s = (const float*)d_in[6];
    const float* Wv_s = (const float*)d_in[7];  const float* bv_s = (const float*)d_in[8];
    const float* Wq_l = (const float*)d_in[9];  const float* bq_l = (const float*)d_in[10];
    const float* Wk_l = (const float*)d_in[11]; const float* bk_l = (const float*)d_in[12];
    const float* Wv_l = (const float*)d_in[13]; const float* bv_l = (const float*)d_in[14];
    const float* Wo   = (const float*)d_in[15]; const float* bo   = (const float*)d_in[16];
    const float* alpha = (const float*)d_in[17];
    const float* beta  = (const float*)d_in[18];
    float* out = (float*)d_out;

    __half *tf, *sf, *vf, *af0, *af1, *af16;
    cudaGetSymbolAddress((void**)&tf, g_tf);
    cudaGetSymbolAddress((void**)&sf, g_sf);
    cudaGetSymbolAddress((void**)&vf, g_vf);
    cudaGetSymbolAddress((void**)&af0, g_af0);
    cudaGetSymbolAddress((void**)&af1, g_af1);
    cudaGetSymbolAddress((void**)&af16, g_af16);

    __half *qs, *ql, *ks, *vs, *kl, *vl;
    cudaGetSymbolAddress((void**)&qs, g_qs); cudaGetSymbolAddress((void**)&ql, g_ql);
    cudaGetSymbolAddress((void**)&ks, g_ks); cudaGetSymbolAddress((void**)&vs, g_vs);
    cudaGetSymbolAddress((void**)&kl, g_kl); cudaGetSymbolAddress((void**)&vl, g_vl);

    __half *wqs, *wql, *wks, *wvs, *wkl, *wvl, *wo;
    cudaGetSymbolAddress((void**)&wqs, g_wqs); cudaGetSymbolAddress((void**)&wql, g_wql);
    cudaGetSymbolAddress((void**)&wks, g_wks); cudaGetSymbolAddress((void**)&wvs, g_wvs);
    cudaGetSymbolAddress((void**)&wkl, g_wkl); cudaGetSymbolAddress((void**)&wvl, g_wvl);
    cudaGetSymbolAddress((void**)&wo,  g_wo);

    cudaFuncSetAttribute(gemm_proj_f16, cudaFuncAttributeMaxDynamicSharedMemorySize, GEMM_SMEM);
    cudaFuncSetAttribute(gemm_out_f16,  cudaFuncAttributeMaxDynamicSharedMemorySize, GEMM_SMEM);
    cudaFuncSetAttribute(attn_mma,      cudaFuncAttributeMaxDynamicSharedMemorySize, ATT_SMEM);

    // --- merged prepass (all fp32 -> fp16) ---
    {
        PrepassParams pp = {};
        const float* Ws[7] = {Wq_s, Wq_l, Wk_s, Wv_s, Wk_l, Wv_l, Wo};
        __half* Ts[7] = {wqs, wql, wks, wvs, wkl, wvl, wo};
        const int Ks[7] = {DMODEL, DMODEL, DLLM, DLLM, DLLM, DLLM, DINNER};
        const int Ns[7] = {DINNER, DINNER, DINNER, DINNER, DINNER, DINNER, DLLM};
        int acc = 0;
        pp.t_ofs[0] = 0;
        for (int i = 0; i < 7; i++) {
            pp.W[i] = Ws[i]; pp.T[i] = Ts[i];
            pp.K[i] = Ks[i]; pp.N[i] = Ns[i];
            acc += (Ks[i] / 32) * (Ns[i] / 32);
            pp.t_ofs[i + 1] = acc;
        }
        pp.total_trans = acc;
        pp.X[0] = target; pp.H[0] = tf;
        pp.X[1] = source; pp.H[1] = sf;
        pp.X[2] = value;  pp.H[2] = vf;
        pp.s_ofs[0] = 0;
        pp.s_ofs[1] = (BL * DMODEL) / 16384;
        pp.s_ofs[2] = pp.s_ofs[1] + (SEQ_S * DLLM) / 16384;
        pp.s_ofs[3] = pp.s_ofs[2] + (SEQ_S * DLLM) / 16384;
        prepass<<<pp.total_trans + pp.s_ofs[3], 256>>>(pp);
    }

    // --- 6 projection GEMMs, one flat launch ---
    {
        ProjJobs p = {};
        const __half* As[6] = {tf, tf, sf, vf, sf, vf};
        const __half* Bs[6] = {wqs, wql, wks, wvs, wkl, wvl};
        const float* bs[6] = {bq_s, bq_l, bk_s, bv_s, bk_l, bv_l};
        __half* Cs[6] = {qs, ql, ks, vs, kl, vl};
        const int Ms[6] = {BL, BL, SEQ_S, SEQ_S, SEQ_S, SEQ_S};
        const int Ks2[6] = {DMODEL, DMODEL, DLLM, DLLM, DLLM, DLLM};
        int acc = 0;
        p.ofs[0] = 0;
        for (int i = 0; i < 6; i++) {
            p.A[i] = As[i]; p.B[i] = Bs[i]; p.bias[i] = bs[i]; p.C[i] = Cs[i];
            p.M[i] = Ms[i]; p.K[i] = Ks2[i];
            acc += 8 * ((Ms[i] + 127) / 128);
            p.ofs[i + 1] = acc;
        }
        gemm_proj_f16<<<acc, 256, GEMM_SMEM>>>(p);
    }

    // --- dual-stream flash attention, streams split across blockIdx.z ---
    {
        AttnParams ap = {};
        ap.q[0] = qs; ap.k[0] = ks; ap.v[0] = vs;
        ap.q[1] = ql; ap.k[1] = kl; ap.v[1] = vl;
        ap.alpha = alpha; ap.beta = beta;
        ap.of[0] = af0; ap.of[1] = af1;
        dim3 g(BL / 128, NHEAD, 2);              // (64, 16, 2) = 2048 blocks
        attn_mma<<<g, 256, ATT_SMEM>>>(ap);
    }

    // --- combine streams: af16 = af0 + af1 ---
    add_f16<<<2048, 256>>>((const __half2*)af0, (const __half2*)af1,
                           (__half2*)af16, BL * DINNER / 2);

    // --- output projection ---
    {
        dim3 g(DLLM / 128, BL / 128);
        gemm_out_f16<<<g, 256, GEMM_SMEM>>>(af16, wo, bo, out);
    }
}

// round 16
// speedup vs baseline: 1.0261x; 1.0261x over previous
#include <cuda_runtime.h>
#include <cuda_fp16.h>
#include <math.h>
#include <stdint.h>

#define BL     8192
#define DMODEL 1024
#define DLLM   4096
#define DINNER 1024
#define SEQ_S  1000
#define NHEAD  16
#define EDIM   64

// ---------------------------------------------------------------------------
// Portable PTX helpers (base compute_103 target — NO tcgen05)
// ---------------------------------------------------------------------------
__device__ __forceinline__ uint32_t smem_u32(const void* p) {
    uint32_t a;
    asm("{ .reg .u64 t; cvta.to.shared.u64 t, %1; cvt.u32.u64 %0, t; }"
        : "=r"(a) : "l"(p));
    return a;
}

#define SWZ(o) ((o) ^ (((o) >> 3) & 0x70))

#define CP_ASYNC16(dst, src) \
    asm volatile("cp.async.cg.shared.global [%0], [%1], 16;\n" :: "r"(dst), "l"(src))
#define CP_COMMIT() asm volatile("cp.async.commit_group;\n" ::: "memory")
#define CP_WAIT1()  asm volatile("cp.async.wait_group 1;\n" ::: "memory")
#define CP_WAIT2()  asm volatile("cp.async.wait_group 2;\n" ::: "memory")
#define CP_WAIT3()  asm volatile("cp.async.wait_group 3;\n" ::: "memory")
#define CP_WAIT0()  asm volatile("cp.async.wait_group 0;\n" ::: "memory")
#define STS_ZERO16(addr) \
    asm volatile("st.shared.v4.b32 [%0], {%1,%1,%1,%1};\n" :: "r"(addr), "r"(0u) : "memory")

__device__ __forceinline__ void ldsm4(uint32_t* r, uint32_t a) {
    asm volatile("ldmatrix.sync.aligned.m8n8.x4.shared.b16 {%0,%1,%2,%3}, [%4];\n"
        : "=r"(r[0]), "=r"(r[1]), "=r"(r[2]), "=r"(r[3]) : "r"(a));
}
__device__ __forceinline__ void ldsm4t(uint32_t* r, uint32_t a) {
    asm volatile("ldmatrix.sync.aligned.m8n8.x4.trans.shared.b16 {%0,%1,%2,%3}, [%4];\n"
        : "=r"(r[0]), "=r"(r[1]), "=r"(r[2]), "=r"(r[3]) : "r"(a));
}
__device__ __forceinline__ void mma16816h(float* c, const uint32_t* a,
                                          uint32_t b0, uint32_t b1) {
    asm volatile(
        "mma.sync.aligned.m16n8k16.row.col.f32.f16.f16.f32 "
        "{%0,%1,%2,%3}, {%4,%5,%6,%7}, {%8,%9}, {%0,%1,%2,%3};\n"
        : "+f"(c[0]), "+f"(c[1]), "+f"(c[2]), "+f"(c[3])
        : "r"(a[0]), "r"(a[1]), "r"(a[2]), "r"(a[3]), "r"(b0), "r"(b1));
}

// ---------------------------------------------------------------------------
// Scratch (device globals — no allocation allowed) — ALL fp16 single
// ---------------------------------------------------------------------------
__device__ __half g_tf[BL * DMODEL];
__device__ __half g_sf[SEQ_S * DLLM];
__device__ __half g_vf[SEQ_S * DLLM];
__device__ __half g_qs[BL * DINNER], g_ql[BL * DINNER];
__device__ __half g_ks[SEQ_S * DINNER], g_vs[SEQ_S * DINNER];
__device__ __half g_kl[SEQ_S * DINNER], g_vl[SEQ_S * DINNER];
__device__ __half g_af16[BL * DINNER];
__device__ __half g_wqs[DINNER * DMODEL], g_wql[DINNER * DMODEL];
__device__ __half g_wks[DINNER * DLLM],   g_wvs[DINNER * DLLM];
__device__ __half g_wkl[DINNER * DLLM],   g_wvl[DINNER * DLLM];
__device__ __half g_wo[DLLM * DINNER];

// ---------------------------------------------------------------------------
// Merged prepass: 7 fp32->fp16 transposes + 3 fp32->fp16 flat converts.
// ---------------------------------------------------------------------------
struct PrepassParams {
    const float* W[7];
    __half* T[7];
    int K[7], N[7];
    int t_ofs[8];
    const float* X[3];
    __half* H[3];
    int s_ofs[4];
    int total_trans;
};

__global__ __launch_bounds__(256)
void prepass(PrepassParams p)
{
    __shared__ float tsm[32][33];
    const int bid = blockIdx.x;
    if (bid < p.total_trans) {
        int w = 0;
        while (bid >= p.t_ofs[w + 1]) w++;
        const int t = bid - p.t_ofs[w];
        const int K = p.K[w], N = p.N[w];
        const int tiles_x = N >> 5;
        const int n0 = (t % tiles_x) << 5, k0 = (t / tiles_x) << 5;
        const float* __restrict__ W = p.W[w];
        __half* __restrict__ T = p.T[w];
        const int tx = threadIdx.x & 31, ty = threadIdx.x >> 5;
#pragma unroll
        for (int i = 0; i < 32; i += 8)
            tsm[ty + i][tx] = W[(size_t)(k0 + ty + i) * N + n0 + tx];
        __syncthreads();
#pragma unroll
        for (int i = 0; i < 32; i += 8) {
            int n = n0 + ty + i;
            T[(size_t)n * K + k0 + tx] = __float2half(tsm[tx][ty + i]);
        }
    } else {
        const int sb = bid - p.total_trans;
        int a = 0;
        while (sb >= p.s_ofs[a + 1]) a++;
        const int rel = sb - p.s_ofs[a];
        const float* __restrict__ X = p.X[a];
        __half* __restrict__ H = p.H[a];
#pragma unroll
        for (int i = 0; i < 16; i++) {
            int idx = rel * 16384 + (i * 256 + threadIdx.x) * 4;
            float4 v = *(const float4*)(X + idx);
            __half2 h01 = __floats2half2_rn(v.x, v.y);
            __half2 h23 = __floats2half2_rn(v.z, v.w);
            uint2 o;
            o.x = *reinterpret_cast<uint32_t*>(&h01);
            o.y = *reinterpret_cast<uint32_t*>(&h23);
            *(uint2*)(H + idx) = o;
        }
    }
}

// ---------------------------------------------------------------------------
// fp16 single-term GEMM, 128x128 tile, BK=64, 3-stage (96KB) -> 2 CTAs/SM.
// ---------------------------------------------------------------------------
#define F_A 0
#define F_B 16384
#define FSTG 32768
#define GEMM_SMEM (3 * FSTG)   // 96 KB

struct ProjJobs {
    const __half *A[6], *B[6];
    const float* bias[6];
    __half* C[6];
    int M[6], K[6];
    int ofs[7];
};

__global__ __launch_bounds__(256, 2)
void gemm_proj_f16(ProjJobs p)
{
    extern __shared__ __align__(1024) char smem[];
    const int bid = blockIdx.x;
    int z = 0;
    while (bid >= p.ofs[z + 1]) z++;
    const int rel = bid - p.ofs[z];
    const int bx = rel & 7, by = rel >> 3;
    const int M = p.M[z], K = p.K[z];
    const int N = DINNER;

    const __half* __restrict__ A = p.A[z];
    const __half* __restrict__ B = p.B[z];

    const int tid = threadIdx.x;
    const int wid = tid >> 5, lid = tid & 31;
    const int wm = wid & 3, wn = wid >> 2;
    const int m0 = by * 128, n0 = bx * 128;
    const uint32_t sb = smem_u32(smem);
    const int NC = K >> 6;

    float c[2][8][4];
#pragma unroll
    for (int i = 0; i < 2; i++)
#pragma unroll
        for (int j = 0; j < 8; j++)
#pragma unroll
            for (int q = 0; q < 4; q++) c[i][j][q] = 0.f;

    auto load_stage = [&](int cchunk) {
        const uint32_t st_ = sb + (cchunk % 3) * FSTG;
        const int k0_ = cchunk << 6;
#pragma unroll
        for (int i_ = 0; i_ < 4; i_++) {
            int idx_ = i_ * 256 + tid;
            int r_ = idx_ >> 3, u_ = idx_ & 7;
            uint32_t sw_ = SWZ((uint32_t)(r_ * 128 + u_ * 16));
            int gm_ = m0 + r_;
            if (gm_ < M)
                CP_ASYNC16(st_ + F_A + sw_, (const char*)(A + (size_t)gm_ * K + k0_) + u_ * 16);
            else
                STS_ZERO16(st_ + F_A + sw_);
            CP_ASYNC16(st_ + F_B + sw_, (const char*)(B + (size_t)(n0 + r_) * K + k0_) + u_ * 16);
        }
        CP_COMMIT();
    };

    load_stage(0);
    load_stage(1);

    const int q8 = lid >> 3, lr = lid & 7;

    for (int cc = 0; cc < NC; cc++) {
        CP_WAIT1();
        __syncthreads();
        if (cc + 2 < NC) { load_stage(cc + 2); } else { CP_COMMIT(); }

        const uint32_t st = sb + (cc % 3) * FSTG;
#pragma unroll
        for (int ks = 0; ks < 4; ks++) {
            const int kb = ks * 32;
            uint32_t ah[2][4], bh[8][2];
#pragma unroll
            for (int mi = 0; mi < 2; mi++) {
                uint32_t off = SWZ((uint32_t)(
                    (wm * 32 + mi * 16 + lr + (q8 & 1) * 8) * 128 + kb + (q8 >> 1) * 16));
                ldsm4(ah[mi], st + F_A + off);
            }
#pragma unroll
            for (int njp = 0; njp < 4; njp++) {
                uint32_t off = SWZ((uint32_t)(
                    (wn * 64 + njp * 16 + lr + (q8 >> 1) * 8) * 128 + kb + (q8 & 1) * 16));
                uint32_t t0[4];
                ldsm4(t0, st + F_B + off);
                bh[2 * njp][0] = t0[0]; bh[2 * njp][1] = t0[1];
                bh[2 * njp + 1][0] = t0[2]; bh[2 * njp + 1][1] = t0[3];
            }
#pragma unroll
            for (int mi = 0; mi < 2; mi++)
#pragma unroll
                for (int nj = 0; nj < 8; nj++)
                    mma16816h(c[mi][nj], ah[mi], bh[nj][0], bh[nj][1]);
        }
    }

    const int lr4 = lid >> 2, lc = (lid & 3) * 2;
    const float* __restrict__ bias = p.bias[z];
    __half* __restrict__ C = p.C[z];
#pragma unroll
    for (int mi = 0; mi < 2; mi++) {
        int row = m0 + wm * 32 + mi * 16 + lr4;
#pragma unroll
        for (int nj = 0; nj < 8; nj++) {
            int col = n0 + wn * 64 + nj * 8 + lc;
            float2 b2 = *(const float2*)(bias + col);
            __half2 h0 = __floats2half2_rn(c[mi][nj][0] + b2.x, c[mi][nj][1] + b2.y);
            __half2 h1 = __floats2half2_rn(c[mi][nj][2] + b2.x, c[mi][nj][3] + b2.y);
            if (row < M)
                *(uint32_t*)(C + (size_t)row * N + col) = *reinterpret_cast<uint32_t*>(&h0);
            if (row + 8 < M)
                *(uint32_t*)(C + (size_t)(row + 8) * N + col) = *reinterpret_cast<uint32_t*>(&h1);
        }
    }
}

__global__ __launch_bounds__(256, 2)
void gemm_out_f16(const __half* __restrict__ A, const __half* __restrict__ B,
                  const float* __restrict__ bias, float* __restrict__ C)
{
    extern __shared__ __align__(1024) char smem[];
    const int tid = threadIdx.x;
    const int wid = tid >> 5, lid = tid & 31;
    const int wm = wid & 3, wn = wid >> 2;
    const int m0 = blockIdx.y * 128, n0 = blockIdx.x * 128;
    const uint32_t sb = smem_u32(smem);
    const int K = DINNER, N = DLLM;
    const int NC = K >> 6;

    float c[2][8][4];
#pragma unroll
    for (int i = 0; i < 2; i++)
#pragma unroll
        for (int j = 0; j < 8; j++)
#pragma unroll
            for (int q = 0; q < 4; q++) c[i][j][q] = 0.f;

    auto load_stage = [&](int cchunk) {
        const uint32_t st_ = sb + (cchunk % 3) * FSTG;
        const int k0_ = cchunk << 6;
#pragma unroll
        for (int i_ = 0; i_ < 4; i_++) {
            int idx_ = i_ * 256 + tid;
            int r_ = idx_ >> 3, u_ = idx_ & 7;
            uint32_t sw_ = SWZ((uint32_t)(r_ * 128 + u_ * 16));
            CP_ASYNC16(st_ + F_A + sw_, (const char*)(A + (size_t)(m0 + r_) * K + k0_) + u_ * 16);
            CP_ASYNC16(st_ + F_B + sw_, (const char*)(B + (size_t)(n0 + r_) * K + k0_) + u_ * 16);
        }
        CP_COMMIT();
    };

    load_stage(0);
    load_stage(1);

    const int q8 = lid >> 3, lr = lid & 7;

    for (int cc = 0; cc < NC; cc++) {
        CP_WAIT1();
        __syncthreads();
        if (cc + 2 < NC) { load_stage(cc + 2); } else { CP_COMMIT(); }

        const uint32_t st = sb + (cc % 3) * FSTG;
#pragma unroll
        for (int ks = 0; ks < 4; ks++) {
            const int kb = ks * 32;
            uint32_t ah[2][4], bh[8][2];
#pragma unroll
            for (int mi = 0; mi < 2; mi++) {
                uint32_t off = SWZ((uint32_t)(
                    (wm * 32 + mi * 16 + lr + (q8 & 1) * 8) * 128 + kb + (q8 >> 1) * 16));
                ldsm4(ah[mi], st + F_A + off);
            }
#pragma unroll
            for (int njp = 0; njp < 4; njp++) {
                uint32_t off = SWZ((uint32_t)(
                    (wn * 64 + njp * 16 + lr + (q8 >> 1) * 8) * 128 + kb + (q8 & 1) * 16));
                uint32_t t0[4];
                ldsm4(t0, st + F_B + off);
                bh[2 * njp][0] = t0[0]; bh[2 * njp][1] = t0[1];
                bh[2 * njp + 1][0] = t0[2]; bh[2 * njp + 1][1] = t0[3];
            }
#pragma unroll
            for (int mi = 0; mi < 2; mi++)
#pragma unroll
                for (int nj = 0; nj < 8; nj++)
                    mma16816h(c[mi][nj], ah[mi], bh[nj][0], bh[nj][1]);
        }
    }

    const int lr4 = lid >> 2, lc = (lid & 3) * 2;
#pragma unroll
    for (int mi = 0; mi < 2; mi++) {
        int row = m0 + wm * 32 + mi * 16 + lr4;
#pragma unroll
        for (int nj = 0; nj < 8; nj++) {
            int col = n0 + wn * 64 + nj * 8 + lc;
            float2 b2 = *(const float2*)(bias + col);
            *(float2*)(C + (size_t)row * N + col) =
                make_float2(c[mi][nj][0] + b2.x, c[mi][nj][1] + b2.y);
            *(float2*)(C + (size_t)(row + 8) * N + col) =
                make_float2(c[mi][nj][2] + b2.x, c[mi][nj][3] + b2.y);
        }
    }
}

// ---------------------------------------------------------------------------
// HMMA flash attention (R14 structure, 4-stage KV pipeline):
// q-tile 128, 8 warps, both streams per CTA, 64KB smem -> 2 CTAs/SM.
// Max-free softmax + MUFU exp (R14 verified). Q staged in stage-3.
// Loop: wait<=2 -> sync -> issue cc+3 : 3 chunks in flight at all times.
// ---------------------------------------------------------------------------
struct AttnParams {
    const __half *q[2], *k[2], *v[2];
    const float *alpha, *beta;
    __half* of;
};

#define ATT_STAGE 16384
#define A_K 0
#define A_V 8192
#define ATT_SMEM (4 * ATT_STAGE)   // 64 KB -> 2 CTAs/SM
#define NCH 16
#define SOFTMAX_SCALE 0.125f

__global__ __launch_bounds__(256, 2)
void attn_mma(AttnParams p)
{
    extern __shared__ __align__(1024) char smem[];
    const uint32_t sb = smem_u32(smem);
    const int tid = threadIdx.x;
    const int w = tid >> 5, lid = tid & 31;
    const int q8 = lid >> 3, lr = lid & 7;
    const int h = blockIdx.y;
    const int qbase = blockIdx.x * 128;
    const int colbase = h * EDIM;

    const float alpha = *p.alpha;
    const float beta  = *p.beta;

    float osave[8][4];

    for (int st = 0; st < 2; st++) {
        const __half* __restrict__ qp = p.q[st];
        const __half* __restrict__ kp = p.k[st];
        const __half* __restrict__ vp = p.v[st];

        // ---- stage Q (128x64 = 16KB) into stage-3 region ----
        const uint32_t qst = sb + 3 * ATT_STAGE;
#pragma unroll
        for (int i = 0; i < 4; i++) {
            int idx = i * 256 + tid;
            int r = idx >> 3, u = idx & 7;
            uint32_t sw = SWZ((uint32_t)(r * 128 + u * 16));
            CP_ASYNC16(qst + sw,
                       (const char*)(qp + (size_t)(qbase + r) * DINNER + colbase) + u * 16);
        }
        CP_COMMIT();

#define LOAD_KV(cchunk) do { \
            const uint32_t stg_ = sb + ((cchunk) & 3) * ATT_STAGE; \
            const int s0_ = (cchunk) * 64; \
            _Pragma("unroll") \
            for (int i_ = 0; i_ < 2; i_++) { \
                int idx_ = i_ * 256 + tid; \
                int r_ = idx_ >> 3, u_ = idx_ & 7; \
                uint32_t sw_ = SWZ((uint32_t)(r_ * 128 + u_ * 16)); \
                if (s0_ + r_ < SEQ_S) { \
                    const size_t go_ = (size_t)(s0_ + r_) * DINNER + colbase; \
                    CP_ASYNC16(stg_ + A_K + sw_, (const char*)(kp + go_) + u_ * 16); \
                    CP_ASYNC16(stg_ + A_V + sw_, (const char*)(vp + go_) + u_ * 16); \
                } else { \
                    STS_ZERO16(stg_ + A_K + sw_); \
                    STS_ZERO16(stg_ + A_V + sw_); \
                } \
            } \
            CP_COMMIT(); \
        } while (0)

        LOAD_KV(0);
        LOAD_KV(1);
        LOAD_KV(2);

        CP_WAIT3();            // <=3 pending => Q (oldest) complete
        __syncthreads();

        uint32_t qf[4][4];
#pragma unroll
        for (int ks = 0; ks < 4; ks++) {
            uint32_t off = SWZ((uint32_t)(
                (w * 16 + lr + (q8 & 1) * 8) * 128 + ks * 32 + (q8 >> 1) * 16));
            ldsm4(qf[ks], qst + off);
        }
        // Stage-3 reuse (chunk 3) is issued only after the first in-loop
        // sync, which orders all warps' qf loads before the overwrite.

        float o[8][4];
#pragma unroll
        for (int t = 0; t < 8; t++)
#pragma unroll
            for (int i = 0; i < 4; i++) o[t][i] = 0.f;
        float l0 = 0.f, l1 = 0.f;

        for (int cc = 0; cc < NCH; cc++) {
            CP_WAIT2();        // <=2 pending => chunk cc complete (FIFO)
            __syncthreads();
            if (cc + 3 < NCH) { LOAD_KV(cc + 3); } else { CP_COMMIT(); }
            const uint32_t stg = sb + (cc & 3) * ATT_STAGE;

            float s[8][4];
#pragma unroll
            for (int t = 0; t < 8; t++)
#pragma unroll
                for (int i = 0; i < 4; i++) s[t][i] = 0.f;

#pragma unroll
            for (int ks = 0; ks < 4; ks++) {
                uint32_t bh[8][2];
#pragma unroll
                for (int njp = 0; njp < 4; njp++) {
                    uint32_t off = SWZ((uint32_t)(
                        (njp * 16 + lr + (q8 >> 1) * 8) * 128 + ks * 32 + (q8 & 1) * 16));
                    uint32_t t0[4];
                    ldsm4(t0, stg + A_K + off);
                    bh[2 * njp][0] = t0[0]; bh[2 * njp][1] = t0[1];
                    bh[2 * njp + 1][0] = t0[2]; bh[2 * njp + 1][1] = t0[3];
                }
#pragma unroll
                for (int t = 0; t < 8; t++)
                    mma16816h(s[t], qf[ks], bh[t][0], bh[t][1]);
            }

            if (cc == NCH - 1) {
#pragma unroll
                for (int t = 5; t < 8; t++)
#pragma unroll
                    for (int i = 0; i < 4; i++) s[t][i] = -1e30f;
            }

            // ---- softmax numerator: max-free, MUFU exp ----
#pragma unroll
            for (int t = 0; t < 8; t++) {
                float p0 = __expf(s[t][0] * SOFTMAX_SCALE);
                float p1 = __expf(s[t][1] * SOFTMAX_SCALE);
                float p2 = __expf(s[t][2] * SOFTMAX_SCALE);
                float p3 = __expf(s[t][3] * SOFTMAX_SCALE);
                l0 += p0 + p1; l1 += p2 + p3;
                s[t][0] = p0; s[t][1] = p1; s[t][2] = p2; s[t][3] = p3;
            }

#pragma unroll
            for (int ks = 0; ks < 4; ks++) {
                uint32_t pa[4];
                __half2 pp0 = __floats2half2_rn(s[2 * ks][0],     s[2 * ks][1]);
                __half2 pp1 = __floats2half2_rn(s[2 * ks][2],     s[2 * ks][3]);
                __half2 pp2 = __floats2half2_rn(s[2 * ks + 1][0], s[2 * ks + 1][1]);
                __half2 pp3 = __floats2half2_rn(s[2 * ks + 1][2], s[2 * ks + 1][3]);
                pa[0] = *reinterpret_cast<uint32_t*>(&pp0);
                pa[1] = *reinterpret_cast<uint32_t*>(&pp1);
                pa[2] = *reinterpret_cast<uint32_t*>(&pp2);
                pa[3] = *reinterpret_cast<uint32_t*>(&pp3);
#pragma unroll
                for (int ep = 0; ep < 4; ep++) {
                    uint32_t off = SWZ((uint32_t)(
                        (ks * 16 + lr + (q8 & 1) * 8) * 128 + ep * 32 + (q8 >> 1) * 16));
                    uint32_t tv0[4];
                    ldsm4t(tv0, stg + A_V + off);
                    mma16816h(o[2 * ep],     pa, tv0[0], tv0[1]);
                    mma16816h(o[2 * ep + 1], pa, tv0[2], tv0[3]);
                }
            }
        }

        l0 += __shfl_xor_sync(0xffffffffu, l0, 1);
        l0 += __shfl_xor_sync(0xffffffffu, l0, 2);
        l1 += __shfl_xor_sync(0xffffffffu, l1, 1);
        l1 += __shfl_xor_sync(0xffffffffu, l1, 2);
        float wgt = (st == 0) ? alpha : beta;
        float f0 = wgt / l0, f1 = wgt / l1;
        if (st == 0) {
#pragma unroll
            for (int t = 0; t < 8; t++) {
                osave[t][0] = o[t][0] * f0; osave[t][1] = o[t][1] * f0;
                osave[t][2] = o[t][2] * f1; osave[t][3] = o[t][3] * f1;
            }
        } else {
#pragma unroll
            for (int t = 0; t < 8; t++) {
                osave[t][0] += o[t][0] * f0; osave[t][1] += o[t][1] * f0;
                osave[t][2] += o[t][2] * f1; osave[t][3] += o[t][3] * f1;
            }
        }
        __syncthreads();   // all warps done with smem before next stream restages
    }

    const int r0 = qbase + w * 16 + (lid >> 2);
#pragma unroll
    for (int t = 0; t < 8; t++) {
        int col = colbase + t * 8 + (lid & 3) * 2;
        __half2 h0 = __floats2half2_rn(osave[t][0], osave[t][1]);
        __half2 h1 = __floats2half2_rn(osave[t][2], osave[t][3]);
        *(uint32_t*)(p.of + (size_t)r0 * DINNER + col) = *reinterpret_cast<uint32_t*>(&h0);
        *(uint32_t*)(p.of + (size_t)(r0 + 8) * DINNER + col) = *reinterpret_cast<uint32_t*>(&h1);
    }
}

// ---------------------------------------------------------------------------
// Launch
// ---------------------------------------------------------------------------
extern "C" void kernel_launch(void* const* d_in, const int* in_sizes, int n_in,
                              void* d_out, int out_size)
{
    const float* target = (const float*)d_in[0];
    const float* source = (const float*)d_in[1];
    const float* value  = (const float*)d_in[2];
    const float* Wq_s = (const float*)d_in[3];  const float* bq_s = (const float*)d_in[4];
    const float* Wk_s = (const float*)d_in[5];  const float* bk_s = (const float*)d_in[6];
    const float* Wv_s = (const float*)d_in[7];  const float* bv_s = (const float*)d_in[8];
    const float* Wq_l = (const float*)d_in[9];  const float* bq_l = (const float*)d_in[10];
    const float* Wk_l = (const float*)d_in[11]; const float* bk_l = (const float*)d_in[12];
    const float* Wv_l = (const float*)d_in[13]; const float* bv_l = (const float*)d_in[14];
    const float* Wo   = (const float*)d_in[15]; const float* bo   = (const float*)d_in[16];
    const float* alpha = (const float*)d_in[17];
    const float* beta  = (const float*)d_in[18];
    float* out = (float*)d_out;

    __half *tf, *sf, *vf, *af16;
    cudaGetSymbolAddress((void**)&tf, g_tf);
    cudaGetSymbolAddress((void**)&sf, g_sf);
    cudaGetSymbolAddress((void**)&vf, g_vf);
    cudaGetSymbolAddress((void**)&af16, g_af16);

    __half *qs, *ql, *ks, *vs, *kl, *vl;
    cudaGetSymbolAddress((void**)&qs, g_qs); cudaGetSymbolAddress((void**)&ql, g_ql);
    cudaGetSymbolAddress((void**)&ks, g_ks); cudaGetSymbolAddress((void**)&vs, g_vs);
    cudaGetSymbolAddress((void**)&kl, g_kl); cudaGetSymbolAddress((void**)&vl, g_vl);

    __half *wqs, *wql, *wks, *wvs, *wkl, *wvl, *wo;
    cudaGetSymbolAddress((void**)&wqs, g_wqs); cudaGetSymbolAddress((void**)&wql, g_wql);
    cudaGetSymbolAddress((void**)&wks, g_wks); cudaGetSymbolAddress((void**)&wvs, g_wvs);
    cudaGetSymbolAddress((void**)&wkl, g_wkl); cudaGetSymbolAddress((void**)&wvl, g_wvl);
    cudaGetSymbolAddress((void**)&wo,  g_wo);

    cudaFuncSetAttribute(gemm_proj_f16, cudaFuncAttributeMaxDynamicSharedMemorySize, GEMM_SMEM);
    cudaFuncSetAttribute(gemm_out_f16,  cudaFuncAttributeMaxDynamicSharedMemorySize, GEMM_SMEM);
    cudaFuncSetAttribute(attn_mma,      cudaFuncAttributeMaxDynamicSharedMemorySize, ATT_SMEM);

    // --- merged prepass (all fp32 -> fp16) ---
    {
        PrepassParams pp = {};
        const float* Ws[7] = {Wq_s, Wq_l, Wk_s, Wv_s, Wk_l, Wv_l, Wo};
        __half* Ts[7] = {wqs, wql, wks, wvs, wkl, wvl, wo};
        const int Ks[7] = {DMODEL, DMODEL, DLLM, DLLM, DLLM, DLLM, DINNER};
        const int Ns[7] = {DINNER, DINNER, DINNER, DINNER, DINNER, DINNER, DLLM};
        int acc = 0;
        pp.t_ofs[0] = 0;
        for (int i = 0; i < 7; i++) {
            pp.W[i] = Ws[i]; pp.T[i] = Ts[i];
            pp.K[i] = Ks[i]; pp.N[i] = Ns[i];
            acc += (Ks[i] / 32) * (Ns[i] / 32);
            pp.t_ofs[i + 1] = acc;
        }
        pp.total_trans = acc;
        pp.X[0] = target; pp.H[0] = tf;
        pp.X[1] = source; pp.H[1] = sf;
        pp.X[2] = value;  pp.H[2] = vf;
        pp.s_ofs[0] = 0;
        pp.s_ofs[1] = (BL * DMODEL) / 16384;
        pp.s_ofs[2] = pp.s_ofs[1] + (SEQ_S * DLLM) / 16384;
        pp.s_ofs[3] = pp.s_ofs[2] + (SEQ_S * DLLM) / 16384;
        prepass<<<pp.total_trans + pp.s_ofs[3], 256>>>(pp);
    }

    // --- 6 projection GEMMs, one flat launch ---
    {
        ProjJobs p = {};
        const __half* As[6] = {tf, tf, sf, vf, sf, vf};
        const __half* Bs[6] = {wqs, wql, wks, wvs, wkl, wvl};
        const float* bs[6] = {bq_s, bq_l, bk_s, bv_s, bk_l, bv_l};
        __half* Cs[6] = {qs, ql, ks, vs, kl, vl};
        const int Ms[6] = {BL, BL, SEQ_S, SEQ_S, SEQ_S, SEQ_S};
        const int Ks2[6] = {DMODEL, DMODEL, DLLM, DLLM, DLLM, DLLM};
        int acc = 0;
        p.ofs[0] = 0;
        for (int i = 0; i < 6; i++) {
            p.A[i] = As[i]; p.B[i] = Bs[i]; p.bias[i] = bs[i]; p.C[i] = Cs[i];
            p.M[i] = Ms[i]; p.K[i] = Ks2[i];
            acc += 8 * ((Ms[i] + 127) / 128);
            p.ofs[i + 1] = acc;
        }
        gemm_proj_f16<<<acc, 256, GEMM_SMEM>>>(p);
    }

    // --- fused dual-stream flash attention (4-stage pipeline) ---
    {
        AttnParams ap = {};
        ap.q[0] = qs; ap.k[0] = ks; ap.v[0] = vs;
        ap.q[1] = ql; ap.k[1] = kl; ap.v[1] = vl;
        ap.alpha = alpha; ap.beta = beta;
        ap.of = af16;
        dim3 g(BL / 128, NHEAD);
        attn_mma<<<g, 256, ATT_SMEM>>>(ap);
    }

    // --- output projection ---
    {
        dim3 g(DLLM / 128, BL / 128);
        gemm_out_f16<<<g, 256, GEMM_SMEM>>>(af16, wo, bo, out);
    }
}